// round 16
// baseline (speedup 1.0000x reference)
#include <cuda_runtime.h>
#include <cuda_fp16.h>
#include <cstdint>

#define A_DIM 384
#define F_DIM 128
#define C_DIM 32
#define H_DIM 512
#define EPS 1e-5f
#define BM 128
#define NTHREADS 1024
#define ROWB 272          // bytes per padded 136-half row (A/H tiles)

// smem byte offsets (total ~139KB -> 1 CTA/SM)
#define A_LN_OFF 0
#define A_H_OFF  34816
#define WB0_OFF  69632            // 32768: weight chunk buffer 0 (256B rows, swizzled)
#define WB1_OFF  102400           // 32768: weight chunk buffer 1
#define MBAR_OFF 135168           // two 8B mbarriers
#define BIAS_OFF 135232
#define SMEM_BYTES (135232 + 4096)
#define CHUNK_BYTES 32768

// device scratch
__device__ float g_left[A_DIM * C_DIM];
__device__ float g_right[A_DIM * C_DIM];
__device__ float g_M[A_DIM * C_DIM * F_DIM];              // M[a][d][f]
__device__ __align__(16) __half g_w1c[4 * 128 * 128];     // chunked+swizzled W1
__device__ __align__(16) __half g_w2c[4 * 128 * 128];     // chunked+swizzled W2

__device__ __forceinline__ uint32_t smem_u32(const void* p) {
    uint32_t a;
    asm("{ .reg .u64 t; cvta.to.shared.u64 t, %1; cvt.u32.u64 %0, t; }" : "=r"(a) : "l"(p));
    return a;
}

#define MBARRIER_INIT(mb, c) \
    asm volatile("mbarrier.init.shared.b64 [%0], %1;" :: "r"((uint32_t)(mb)), "r"((uint32_t)(c)) : "memory")

__device__ __forceinline__ void issue_bulk(uint32_t dst, const void* src, uint32_t mbar) {
    asm volatile("mbarrier.arrive.expect_tx.shared.b64 _, [%0], %1;"
                 :: "r"(mbar), "r"((uint32_t)CHUNK_BYTES) : "memory");
    asm volatile("cp.async.bulk.shared::cluster.global.mbarrier::complete_tx::bytes "
                 "[%0], [%1], %2, [%3];"
                 :: "r"(dst), "l"(src), "r"((uint32_t)CHUNK_BYTES), "r"(mbar) : "memory");
}

#define MBARRIER_WAIT_PARITY(mb, par) do {                                      \
    uint32_t _mb = (uint32_t)(mb), _p = (uint32_t)(par), _done;                 \
    asm volatile("{\n\t.reg .pred p;\n\t"                                       \
        "mbarrier.try_wait.parity.acquire.cta.shared::cta.b64 p, [%1], %2;\n\t" \
        "selp.b32 %0, 1, 0, p;\n\t}" : "=r"(_done) : "r"(_mb), "r"(_p) : "memory"); \
    if (!_done) {                                                               \
        asm volatile("{\n\t.reg .pred P1;\n\t"                                  \
            "W%=:\n\t"                                                          \
            "mbarrier.try_wait.parity.acquire.cta.shared::cta.b64 P1, [%0], %1, 0x989680;\n\t" \
            "@P1 bra.uni D%=;\n\t"                                              \
            "bra.uni W%=;\n\t"                                                  \
            "D%=:\n\t}" :: "r"(_mb), "r"(_p) : "memory");                       \
    }                                                                           \
} while (0)

__device__ __forceinline__ void ldsm4(uint32_t& r0, uint32_t& r1, uint32_t& r2,
                                      uint32_t& r3, uint32_t addr) {
    asm volatile("ldmatrix.sync.aligned.m8n8.x4.shared.b16 {%0,%1,%2,%3}, [%4];"
                 : "=r"(r0), "=r"(r1), "=r"(r2), "=r"(r3) : "r"(addr));
}
__device__ __forceinline__ void ldsm4t(uint32_t& r0, uint32_t& r1, uint32_t& r2,
                                       uint32_t& r3, uint32_t addr) {
    asm volatile("ldmatrix.sync.aligned.m8n8.x4.trans.shared.b16 {%0,%1,%2,%3}, [%4];"
                 : "=r"(r0), "=r"(r1), "=r"(r2), "=r"(r3) : "r"(addr));
}
__device__ __forceinline__ void mma_f16(float c[4], uint32_t a0, uint32_t a1,
                                        uint32_t a2, uint32_t a3,
                                        uint32_t b0, uint32_t b1) {
    asm volatile(
        "mma.sync.aligned.m16n8k16.row.col.f32.f16.f16.f32 "
        "{%0,%1,%2,%3}, {%4,%5,%6,%7}, {%8,%9}, {%0,%1,%2,%3};"
        : "+f"(c[0]), "+f"(c[1]), "+f"(c[2]), "+f"(c[3])
        : "r"(a0), "r"(a1), "r"(a2), "r"(a3), "r"(b0), "r"(b1));
}

// ---- packed f32x2 helpers ----
__device__ __forceinline__ unsigned long long pack2(float lo, float hi) {
    unsigned long long r;
    asm("mov.b64 %0, {%1, %2};" : "=l"(r) : "f"(lo), "f"(hi));
    return r;
}
__device__ __forceinline__ void unpack2(float& lo, float& hi, unsigned long long v) {
    asm("mov.b64 {%0, %1}, %2;" : "=f"(lo), "=f"(hi) : "l"(v));
}
__device__ __forceinline__ void fma2(unsigned long long& d, unsigned long long a,
                                     unsigned long long b) {
    asm("fma.rn.f32x2 %0, %1, %2, %0;" : "+l"(d) : "l"(a), "l"(b));
}

// ---------------------------------------------------------------------------
// Kernel 1: node LN -> left/right (masked); weight cvt into chunked+swizzled
// fp16 layout: chunk jc row k, 16B seg s placed at seg (s ^ (k&7)).
// ---------------------------------------------------------------------------
__global__ void k_pre(const float* __restrict__ node_vec,
                      const float* __restrict__ node_mask,
                      const float* __restrict__ ln_scale,
                      const float* __restrict__ ln_bias,
                      const float* __restrict__ w_left,
                      const float* __restrict__ b_left,
                      const float* __restrict__ w_right,
                      const float* __restrict__ b_right,
                      const float* __restrict__ w_t1,
                      const float* __restrict__ w_t2) {
    int a = blockIdx.x;
    int t = threadIdx.x;
    __shared__ float act[F_DIM];
    __shared__ float red[4];

    for (int idx = a * 128 + t; idx < 131072; idx += 384 * 128) {
        if (idx < 65536) {
            int k = idx >> 9, n = idx & 511;
            int jc = n >> 7, nn = n & 127;
            int dst = ((jc * 128 + k) << 7) + ((((nn >> 3) ^ (k & 7)) << 3) | (nn & 7));
            g_w1c[dst] = __float2half_rn(w_t1[idx]);
        } else {
            int i2 = idx - 65536;
            int row = i2 >> 7, n = i2 & 127;
            int jc = row >> 7, k = row & 127;
            int dst = ((jc * 128 + k) << 7) + ((((n >> 3) ^ (k & 7)) << 3) | (n & 7));
            g_w2c[dst] = __float2half_rn(w_t2[i2]);
        }
    }

    float x = node_vec[a * F_DIM + t];
    float s = x;
    #pragma unroll
    for (int o = 16; o; o >>= 1) s += __shfl_xor_sync(~0u, s, o);
    if ((t & 31) == 0) red[t >> 5] = s;
    __syncthreads();
    float mu = (red[0] + red[1] + red[2] + red[3]) * (1.0f / F_DIM);
    __syncthreads();
    float d = x - mu;
    float s2 = d * d;
    #pragma unroll
    for (int o = 16; o; o >>= 1) s2 += __shfl_xor_sync(~0u, s2, o);
    if ((t & 31) == 0) red[t >> 5] = s2;
    __syncthreads();
    float var = (red[0] + red[1] + red[2] + red[3]) * (1.0f / F_DIM);
    float rstd = rsqrtf(var + EPS);
    act[t] = d * rstd * ln_scale[t] + ln_bias[t];
    __syncthreads();

    float nm = node_mask[a];
    if (t < C_DIM) {
        float acc = b_left[t];
        #pragma unroll 8
        for (int f = 0; f < F_DIM; f++) acc += act[f] * w_left[f * C_DIM + t];
        g_left[a * C_DIM + t] = acc * nm;
    } else if (t < 2 * C_DIM) {
        int c = t - C_DIM;
        float acc = b_right[c];
        #pragma unroll 8
        for (int f = 0; f < F_DIM; f++) acc += act[f] * w_right[f * C_DIM + c];
        g_right[a * C_DIM + c] = acc * nm;
    }
}

// ---------------------------------------------------------------------------
// Kernel 2: M[a][d][f] = sum_c left[a,c] * w_out[(c*32+d)*128 + f]
// ---------------------------------------------------------------------------
__global__ __launch_bounds__(512)
void k_M(const float* __restrict__ w_out) {
    int a0 = blockIdx.x * 8;
    int tid = threadIdx.x;
    int f = tid & 127;
    int d0 = (tid >> 7) * 8;
    __shared__ float s_left[8][C_DIM];
    if (tid < 256) s_left[tid >> 5][tid & 31] = g_left[(a0 + (tid >> 5)) * C_DIM + (tid & 31)];
    __syncthreads();

    float acc[8][8];
    #pragma unroll
    for (int i = 0; i < 8; i++)
        #pragma unroll
        for (int j = 0; j < 8; j++) acc[i][j] = 0.0f;

    for (int c = 0; c < C_DIM; c++) {
        float w[8];
        #pragma unroll
        for (int j = 0; j < 8; j++)
            w[j] = w_out[(c * C_DIM + d0 + j) * F_DIM + f];
        #pragma unroll
        for (int i = 0; i < 8; i++) {
            float lv = s_left[i][c];
            #pragma unroll
            for (int j = 0; j < 8; j++) acc[i][j] += lv * w[j];
        }
    }
    #pragma unroll
    for (int i = 0; i < 8; i++)
        #pragma unroll
        for (int j = 0; j < 8; j++)
            g_M[((a0 + i) * C_DIM + d0 + j) * F_DIM + f] = acc[i][j];
}

// ---------------------------------------------------------------------------
// One 128x128x128 chunk GEMM; 32 warps, warp tile 16x32.
// A tile: 272B rows (ldsm4). W tile: 256B rows, gmem-preswizzled (ldsm4t).
// ---------------------------------------------------------------------------
__device__ __forceinline__ void gemm_chunk(uint32_t Abase, uint32_t Wbase,
                                           int lane, int m0, int n0,
                                           float (&acc)[4][4]) {
    const uint32_t a_off = Abase + (uint32_t)(m0 + (lane & 15)) * ROWB + (lane >> 4) * 16;
    const int rb = ((lane >> 3) & 1) * 8 + (lane & 7);   // 0..15
    const int s0 = (n0 >> 3) + (lane >> 4);              // base 16B segment
    const uint32_t b_base0 = Wbase + (uint32_t)rb * 256 +
                             ((uint32_t)((s0 + 0) ^ (rb & 7)) << 4);
    const uint32_t b_base1 = Wbase + (uint32_t)rb * 256 +
                             ((uint32_t)((s0 + 2) ^ (rb & 7)) << 4);

    #pragma unroll
    for (int ks = 0; ks < 8; ks++) {
        const uint32_t k0 = ks * 16;
        uint32_t a0r, a1r, a2r, a3r;
        ldsm4(a0r, a1r, a2r, a3r, a_off + k0 * 2);
        uint32_t b[4][2];
        {
            uint32_t r0, r1, r2, r3;
            ldsm4t(r0, r1, r2, r3, b_base0 + ks * 4096);
            b[0][0] = r0; b[0][1] = r1; b[1][0] = r2; b[1][1] = r3;
            ldsm4t(r0, r1, r2, r3, b_base1 + ks * 4096);
            b[2][0] = r0; b[2][1] = r1; b[3][0] = r2; b[3][1] = r3;
        }
        #pragma unroll
        for (int nb = 0; nb < 4; nb++)
            mma_f16(acc[nb], a0r, a1r, a2r, a3r, b[nb][0], b[nb][1]);
    }
}

// ---------------------------------------------------------------------------
// Kernel 3: fused main kernel. grid = (3, 384), 1024 threads, 1 CTA/SM.
// R9 schedule; weights staged by cp.async.bulk (1 instr / 32KB chunk).
// ---------------------------------------------------------------------------
__global__ __launch_bounds__(NTHREADS, 1)
void k_main(const float* __restrict__ edge_vec,
            const float* __restrict__ b_out,
            const float* __restrict__ tr_scale,
            const float* __restrict__ tr_bias,
            const float* __restrict__ b_t1,
            const float* __restrict__ b_t2,
            float* __restrict__ out) {
    extern __shared__ char smem[];
    const uint32_t sb = smem_u32(smem);
    const int tid = threadIdx.x;
    const int wid = tid >> 5;
    const int lane = tid & 31;
    const int a = blockIdx.y;
    const int bb = blockIdx.x * BM;

    const uint32_t mb0 = sb + MBAR_OFF;
    const uint32_t mb1 = sb + MBAR_OFF + 8;
    const uint32_t Wb0 = sb + WB0_OFF;
    const uint32_t Wb1 = sb + WB1_OFF;

    if (tid == 0) {
        MBARRIER_INIT(mb0, 1);
        MBARRIER_INIT(mb1, 1);
        issue_bulk(Wb0, g_w1c, mb0);             // W1 chunk 0
        issue_bulk(Wb1, g_w2c, mb1);             // W2 chunk 0
    }

    float* s_bias32 = (float*)(smem + BIAS_OFF);
    float* s_scale = s_bias32;
    float* s_bias  = s_bias32 + 128;
    float* s_b1    = s_bias32 + 256;
    float* s_b2    = s_bias32 + 768;
    float* s_bout  = s_bias32 + 896;
    for (int i = tid; i < F_DIM; i += NTHREADS) {
        s_scale[i] = tr_scale[i];
        s_bias[i]  = tr_bias[i];
        s_b2[i]    = b_t2[i];
        s_bout[i]  = b_out[i];
    }
    for (int i = tid; i < H_DIM; i += NTHREADS) s_b1[i] = b_t1[i];

    // stage m_a + right into A_H region (fp32 overlays)
    float* Sf = (float*)(smem + A_H_OFF);
    for (int idx = tid; idx < C_DIM * F_DIM; idx += NTHREADS)
        Sf[idx] = g_M[a * C_DIM * F_DIM + idx];               // m_a[d][f]
    for (int idx = tid; idx < BM * C_DIM; idx += NTHREADS) {
        int r = idx >> 5, c = idx & 31;
        Sf[4096 + r * 33 + c] = g_right[(bb + r) * C_DIM + c];
    }
    __syncthreads();

    // ---- e = right @ M_a + edge + b_out (fp32, f32x2) -> gmem; LN -> A_LN fp16
    {
        const int ty = tid >> 4, tx = tid & 15;
        const int r0 = ty * 2, c0 = tx * 8;
        unsigned long long acc2[2][4];
        #pragma unroll
        for (int i = 0; i < 2; i++)
            #pragma unroll
            for (int q = 0; q < 4; q++) acc2[i][q] = 0ull;

        #pragma unroll 4
        for (int k = 0; k < C_DIM; k++) {
            ulonglong2 bA = *reinterpret_cast<const ulonglong2*>(Sf + k * 128 + c0);
            ulonglong2 bB = *reinterpret_cast<const ulonglong2*>(Sf + k * 128 + c0 + 4);
            unsigned long long bv2[4] = { bA.x, bA.y, bB.x, bB.y };
            #pragma unroll
            for (int i = 0; i < 2; i++) {
                float av = Sf[4096 + (r0 + i) * 33 + k];
                unsigned long long av2 = pack2(av, av);
                #pragma unroll
                for (int q = 0; q < 4; q++) fma2(acc2[i][q], av2, bv2[q]);
            }
        }
        float acc[2][8];
        #pragma unroll
        for (int i = 0; i < 2; i++)
            #pragma unroll
            for (int q = 0; q < 4; q++)
                unpack2(acc[i][q * 2], acc[i][q * 2 + 1], acc2[i][q]);

        const float* ep = edge_vec + ((long)(a * A_DIM) + bb) * F_DIM;
        float* op = out + ((long)(a * A_DIM) + bb) * F_DIM;
        float rs[2], rq[2];
        #pragma unroll
        for (int i = 0; i < 2; i++) {
            const int r = r0 + i;
            float4 e0 = *reinterpret_cast<const float4*>(ep + r * F_DIM + c0);
            float4 e1 = *reinterpret_cast<const float4*>(ep + r * F_DIM + c0 + 4);
            acc[i][0] += e0.x + s_bout[c0+0]; acc[i][1] += e0.y + s_bout[c0+1];
            acc[i][2] += e0.z + s_bout[c0+2]; acc[i][3] += e0.w + s_bout[c0+3];
            acc[i][4] += e1.x + s_bout[c0+4]; acc[i][5] += e1.y + s_bout[c0+5];
            acc[i][6] += e1.z + s_bout[c0+6]; acc[i][7] += e1.w + s_bout[c0+7];
            float4 o0 = make_float4(acc[i][0], acc[i][1], acc[i][2], acc[i][3]);
            float4 o1 = make_float4(acc[i][4], acc[i][5], acc[i][6], acc[i][7]);
            *reinterpret_cast<float4*>(op + r * F_DIM + c0) = o0;
            *reinterpret_cast<float4*>(op + r * F_DIM + c0 + 4) = o1;
            float s = 0.0f, q = 0.0f;
            #pragma unroll
            for (int j = 0; j < 8; j++) { s += acc[i][j]; q += acc[i][j] * acc[i][j]; }
            rs[i] = s; rq[i] = q;
        }
        #pragma unroll
        for (int off = 1; off < 16; off <<= 1) {
            #pragma unroll
            for (int i = 0; i < 2; i++) {
                rs[i] += __shfl_xor_sync(~0u, rs[i], off);
                rq[i] += __shfl_xor_sync(~0u, rq[i], off);
            }
        }
        #pragma unroll
        for (int i = 0; i < 2; i++) {
            const float mu = rs[i] * (1.0f / F_DIM);
            const float var = rq[i] * (1.0f / F_DIM) - mu * mu;
            const float rstd = rsqrtf(var + EPS);
            __half2 h[4];
            #pragma unroll
            for (int jq = 0; jq < 4; jq++) {
                float l0 = (acc[i][jq*2+0] - mu) * rstd * s_scale[c0+jq*2+0] + s_bias[c0+jq*2+0];
                float l1 = (acc[i][jq*2+1] - mu) * rstd * s_scale[c0+jq*2+1] + s_bias[c0+jq*2+1];
                h[jq] = __floats2half2_rn(l0, l1);
            }
            *reinterpret_cast<uint4*>(smem + A_LN_OFF + (r0 + i) * ROWB + c0 * 2) =
                *reinterpret_cast<uint4*>(h);
        }
    }
    __syncthreads();

    // ---- transition MLP: 4 j-chunks (R9 schedule; bulk-staged weights) ----
    const int m0 = (wid >> 2) * 16;
    const int n0 = (wid & 3) * 32;
    const int g = lane >> 2, tig = lane & 3;
    const uint32_t Aln = sb + A_LN_OFF;
    const uint32_t Ah  = sb + A_H_OFF;

    float oacc[4][4];
    #pragma unroll
    for (int nb = 0; nb < 4; nb++)
        #pragma unroll
        for (int q = 0; q < 4; q++) oacc[nb][q] = 0.0f;

    int p0 = 0, p1 = 0;
    #pragma unroll 1
    for (int jc = 0; jc < 4; jc++) {
        float hacc[4][4];
        #pragma unroll
        for (int nb = 0; nb < 4; nb++)
            #pragma unroll
            for (int q = 0; q < 4; q++) hacc[nb][q] = 0.0f;

        MBARRIER_WAIT_PARITY(mb0, p0); p0 ^= 1;       // W1_jc resident
        __syncthreads();
        gemm_chunk(Aln, Wb0, lane, m0, n0, hacc);
        __syncthreads();                               // WB0 free
        if (jc < 3 && tid == 0)
            issue_bulk(Wb0, g_w1c + (jc + 1) * 16384, mb0);

        {
            const int r = m0 + g;
            #pragma unroll
            for (int nb = 0; nb < 4; nb++) {
                const int c = n0 + nb * 8 + 2 * tig;
                const float b0 = s_b1[jc * 128 + c];
                const float b1 = s_b1[jc * 128 + c + 1];
                __half2 v0 = __floats2half2_rn(fmaxf(hacc[nb][0] + b0, 0.0f),
                                               fmaxf(hacc[nb][1] + b1, 0.0f));
                __half2 v1 = __floats2half2_rn(fmaxf(hacc[nb][2] + b0, 0.0f),
                                               fmaxf(hacc[nb][3] + b1, 0.0f));
                *reinterpret_cast<__half2*>(smem + A_H_OFF + r * ROWB + c * 2) = v0;
                *reinterpret_cast<__half2*>(smem + A_H_OFF + (r + 8) * ROWB + c * 2) = v1;
            }
        }
        MBARRIER_WAIT_PARITY(mb1, p1); p1 ^= 1;       // W2_jc resident
        __syncthreads();                               // h visible
        gemm_chunk(Ah, Wb1, lane, m0, n0, oacc);
        __syncthreads();                               // WB1 free
        if (jc < 3 && tid == 0)
            issue_bulk(Wb1, g_w2c + (jc + 1) * 16384, mb1);
    }

    // ---- epilogue: out = e + O + b_t2 ----
    {
        float* op = out + ((long)(a * A_DIM) + bb) * F_DIM;
        const int r = m0 + g;
        #pragma unroll
        for (int nb = 0; nb < 4; nb++) {
            const int c = n0 + nb * 8 + 2 * tig;
            const float b20 = s_b2[c], b21 = s_b2[c + 1];
            float2 e0 = *reinterpret_cast<const float2*>(op + r * F_DIM + c);
            float2 e1 = *reinterpret_cast<const float2*>(op + (r + 8) * F_DIM + c);
            float2 o0, o1;
            o0.x = e0.x + oacc[nb][0] + b20;
            o0.y = e0.y + oacc[nb][1] + b21;
            o1.x = e1.x + oacc[nb][2] + b20;
            o1.y = e1.y + oacc[nb][3] + b21;
            *reinterpret_cast<float2*>(op + r * F_DIM + c) = o0;
            *reinterpret_cast<float2*>(op + (r + 8) * F_DIM + c) = o1;
        }
    }
}

// ---------------------------------------------------------------------------
// Launch
// ---------------------------------------------------------------------------
extern "C" void kernel_launch(void* const* d_in, const int* in_sizes, int n_in,
                              void* d_out, int out_size) {
    const float* node_vec    = (const float*)d_in[0];
    const float* edge_vec    = (const float*)d_in[1];
    const float* node_mask   = (const float*)d_in[2];
    const float* op_ln_scale = (const float*)d_in[4];
    const float* op_ln_bias  = (const float*)d_in[5];
    const float* w_left      = (const float*)d_in[6];
    const float* b_left      = (const float*)d_in[7];
    const float* w_right     = (const float*)d_in[8];
    const float* b_right     = (const float*)d_in[9];
    const float* w_out       = (const float*)d_in[10];
    const float* b_out       = (const float*)d_in[11];
    const float* tr_ln_scale = (const float*)d_in[12];
    const float* tr_ln_bias  = (const float*)d_in[13];
    const float* w_t1        = (const float*)d_in[14];
    const float* b_t1        = (const float*)d_in[15];
    const float* w_t2        = (const float*)d_in[16];
    const float* b_t2        = (const float*)d_in[17];
    float* out = (float*)d_out;

    static bool attr_set = false;
    if (!attr_set) {
        cudaFuncSetAttribute(k_main, cudaFuncAttributeMaxDynamicSharedMemorySize,
                             (int)SMEM_BYTES);
        attr_set = true;
    }

    k_pre<<<A_DIM, F_DIM>>>(node_vec, node_mask, op_ln_scale, op_ln_bias,
                            w_left, b_left, w_right, b_right, w_t1, w_t2);
    k_M<<<A_DIM / 8, 512>>>(w_out);
    k_main<<<dim3(A_DIM / BM, A_DIM), NTHREADS, SMEM_BYTES>>>(
        edge_vec, b_out, tr_ln_scale, tr_ln_bias, b_t1, b_t2, out);
}

// round 17
// speedup vs baseline: 1.3549x; 1.3549x over previous
#include <cuda_runtime.h>
#include <cuda_fp16.h>
#include <cstdint>

#define A_DIM 384
#define F_DIM 128
#define C_DIM 32
#define H_DIM 512
#define EPS 1e-5f
#define BM 128
#define NTHREADS 512
#define ROWB 272          // bytes per padded 136-half row (A/H tiles)

// smem byte offsets (total ~139KB -> 1 CTA/SM)
#define A_LN_OFF 0
#define A_H_OFF  34816
#define WB0_OFF  69632            // 32768: weight chunk buffer 0 (256B rows, swizzled)
#define WB1_OFF  102400           // 32768: weight chunk buffer 1
#define MBAR_OFF 135168           // three 8B mbarriers
#define BIAS_OFF 135232
#define SMEM_BYTES (135232 + 4096)
#define CHUNK_BYTES 32768

// device scratch
__device__ float g_left[A_DIM * C_DIM];
__device__ __align__(16) float g_rightB[A_DIM * C_DIM];   // blocked: [b_tile][c][128]
__device__ __align__(16) float g_M[A_DIM * C_DIM * F_DIM];
__device__ __align__(16) __half g_w1c[4 * 128 * 128];     // chunked+swizzled W1
__device__ __align__(16) __half g_w2c[4 * 128 * 128];     // chunked+swizzled W2

__device__ __forceinline__ uint32_t smem_u32(const void* p) {
    uint32_t a;
    asm("{ .reg .u64 t; cvta.to.shared.u64 t, %1; cvt.u32.u64 %0, t; }" : "=r"(a) : "l"(p));
    return a;
}

#define MBARRIER_INIT(mb, c) \
    asm volatile("mbarrier.init.shared.b64 [%0], %1;" :: "r"((uint32_t)(mb)), "r"((uint32_t)(c)) : "memory")

__device__ __forceinline__ void expect_tx(uint32_t mbar, uint32_t bytes) {
    asm volatile("mbarrier.arrive.expect_tx.shared.b64 _, [%0], %1;"
                 :: "r"(mbar), "r"(bytes) : "memory");
}
__device__ __forceinline__ void bulk_cp(uint32_t dst, const void* src, uint32_t bytes,
                                        uint32_t mbar) {
    asm volatile("cp.async.bulk.shared::cluster.global.mbarrier::complete_tx::bytes "
                 "[%0], [%1], %2, [%3];"
                 :: "r"(dst), "l"(src), "r"(bytes), "r"(mbar) : "memory");
}
__device__ __forceinline__ void issue_bulk(uint32_t dst, const void* src, uint32_t mbar) {
    expect_tx(mbar, CHUNK_BYTES);
    bulk_cp(dst, src, CHUNK_BYTES, mbar);
}

#define MBARRIER_WAIT_PARITY(mb, par) do {                                      \
    uint32_t _mb = (uint32_t)(mb), _p = (uint32_t)(par), _done;                 \
    asm volatile("{\n\t.reg .pred p;\n\t"                                       \
        "mbarrier.try_wait.parity.acquire.cta.shared::cta.b64 p, [%1], %2;\n\t" \
        "selp.b32 %0, 1, 0, p;\n\t}" : "=r"(_done) : "r"(_mb), "r"(_p) : "memory"); \
    if (!_done) {                                                               \
        asm volatile("{\n\t.reg .pred P1;\n\t"                                  \
            "W%=:\n\t"                                                          \
            "mbarrier.try_wait.parity.acquire.cta.shared::cta.b64 P1, [%0], %1, 0x989680;\n\t" \
            "@P1 bra.uni D%=;\n\t"                                              \
            "bra.uni W%=;\n\t"                                                  \
            "D%=:\n\t}" :: "r"(_mb), "r"(_p) : "memory");                       \
    }                                                                           \
} while (0)

__device__ __forceinline__ void ldsm4(uint32_t& r0, uint32_t& r1, uint32_t& r2,
                                      uint32_t& r3, uint32_t addr) {
    asm volatile("ldmatrix.sync.aligned.m8n8.x4.shared.b16 {%0,%1,%2,%3}, [%4];"
                 : "=r"(r0), "=r"(r1), "=r"(r2), "=r"(r3) : "r"(addr));
}
__device__ __forceinline__ void ldsm4t(uint32_t& r0, uint32_t& r1, uint32_t& r2,
                                       uint32_t& r3, uint32_t addr) {
    asm volatile("ldmatrix.sync.aligned.m8n8.x4.trans.shared.b16 {%0,%1,%2,%3}, [%4];"
                 : "=r"(r0), "=r"(r1), "=r"(r2), "=r"(r3) : "r"(addr));
}
__device__ __forceinline__ void mma_f16(float c[4], uint32_t a0, uint32_t a1,
                                        uint32_t a2, uint32_t a3,
                                        uint32_t b0, uint32_t b1) {
    asm volatile(
        "mma.sync.aligned.m16n8k16.row.col.f32.f16.f16.f32 "
        "{%0,%1,%2,%3}, {%4,%5,%6,%7}, {%8,%9}, {%0,%1,%2,%3};"
        : "+f"(c[0]), "+f"(c[1]), "+f"(c[2]), "+f"(c[3])
        : "r"(a0), "r"(a1), "r"(a2), "r"(a3), "r"(b0), "r"(b1));
}

// ---- packed f32x2 helpers ----
__device__ __forceinline__ unsigned long long pack2(float lo, float hi) {
    unsigned long long r;
    asm("mov.b64 %0, {%1, %2};" : "=l"(r) : "f"(lo), "f"(hi));
    return r;
}
__device__ __forceinline__ void unpack2(float& lo, float& hi, unsigned long long v) {
    asm("mov.b64 {%0, %1}, %2;" : "=f"(lo), "=f"(hi) : "l"(v));
}
__device__ __forceinline__ void fma2(unsigned long long& d, unsigned long long a,
                                     unsigned long long b) {
    asm("fma.rn.f32x2 %0, %1, %2, %0;" : "+l"(d) : "l"(a), "l"(b));
}

// ---------------------------------------------------------------------------
// Kernel 1: node LN -> left/right (masked, right in blocked layout);
// weight cvt into chunked+swizzled fp16 layout.
// ---------------------------------------------------------------------------
__global__ void k_pre(const float* __restrict__ node_vec,
                      const float* __restrict__ node_mask,
                      const float* __restrict__ ln_scale,
                      const float* __restrict__ ln_bias,
                      const float* __restrict__ w_left,
                      const float* __restrict__ b_left,
                      const float* __restrict__ w_right,
                      const float* __restrict__ b_right,
                      const float* __restrict__ w_t1,
                      const float* __restrict__ w_t2) {
    int a = blockIdx.x;
    int t = threadIdx.x;
    __shared__ float act[F_DIM];
    __shared__ float red[4];

    for (int idx = a * 128 + t; idx < 131072; idx += 384 * 128) {
        if (idx < 65536) {
            int k = idx >> 9, n = idx & 511;
            int jc = n >> 7, nn = n & 127;
            int dst = ((jc * 128 + k) << 7) + ((((nn >> 3) ^ (k & 7)) << 3) | (nn & 7));
            g_w1c[dst] = __float2half_rn(w_t1[idx]);
        } else {
            int i2 = idx - 65536;
            int row = i2 >> 7, n = i2 & 127;
            int jc = row >> 7, k = row & 127;
            int dst = ((jc * 128 + k) << 7) + ((((n >> 3) ^ (k & 7)) << 3) | (n & 7));
            g_w2c[dst] = __float2half_rn(w_t2[i2]);
        }
    }

    float x = node_vec[a * F_DIM + t];
    float s = x;
    #pragma unroll
    for (int o = 16; o; o >>= 1) s += __shfl_xor_sync(~0u, s, o);
    if ((t & 31) == 0) red[t >> 5] = s;
    __syncthreads();
    float mu = (red[0] + red[1] + red[2] + red[3]) * (1.0f / F_DIM);
    __syncthreads();
    float d = x - mu;
    float s2 = d * d;
    #pragma unroll
    for (int o = 16; o; o >>= 1) s2 += __shfl_xor_sync(~0u, s2, o);
    if ((t & 31) == 0) red[t >> 5] = s2;
    __syncthreads();
    float var = (red[0] + red[1] + red[2] + red[3]) * (1.0f / F_DIM);
    float rstd = rsqrtf(var + EPS);
    act[t] = d * rstd * ln_scale[t] + ln_bias[t];
    __syncthreads();

    float nm = node_mask[a];
    if (t < C_DIM) {
        float acc = b_left[t];
        #pragma unroll 8
        for (int f = 0; f < F_DIM; f++) acc += act[f] * w_left[f * C_DIM + t];
        g_left[a * C_DIM + t] = acc * nm;
    } else if (t < 2 * C_DIM) {
        int c = t - C_DIM;
        float acc = b_right[c];
        #pragma unroll 8
        for (int f = 0; f < F_DIM; f++) acc += act[f] * w_right[f * C_DIM + c];
        // blocked layout: [a>>7][c][a&127]
        g_rightB[((a >> 7) << 12) + (c << 7) + (a & 127)] = acc * nm;
    }
}

// ---------------------------------------------------------------------------
// Kernel 2: M[a][d][f] = sum_c left[a,c] * w_out[(c*32+d)*128 + f]
// ---------------------------------------------------------------------------
__global__ __launch_bounds__(512)
void k_M(const float* __restrict__ w_out) {
    int a0 = blockIdx.x * 8;
    int tid = threadIdx.x;
    int f = tid & 127;
    int d0 = (tid >> 7) * 8;
    __shared__ float s_left[8][C_DIM];
    if (tid < 256) s_left[tid >> 5][tid & 31] = g_left[(a0 + (tid >> 5)) * C_DIM + (tid & 31)];
    __syncthreads();

    float acc[8][8];
    #pragma unroll
    for (int i = 0; i < 8; i++)
        #pragma unroll
        for (int j = 0; j < 8; j++) acc[i][j] = 0.0f;

    for (int c = 0; c < C_DIM; c++) {
        float w[8];
        #pragma unroll
        for (int j = 0; j < 8; j++)
            w[j] = w_out[(c * C_DIM + d0 + j) * F_DIM + f];
        #pragma unroll
        for (int i = 0; i < 8; i++) {
            float lv = s_left[i][c];
            #pragma unroll
            for (int j = 0; j < 8; j++) acc[i][j] += lv * w[j];
        }
    }
    #pragma unroll
    for (int i = 0; i < 8; i++)
        #pragma unroll
        for (int j = 0; j < 8; j++)
            g_M[((a0 + i) * C_DIM + d0 + j) * F_DIM + f] = acc[i][j];
}

// ---------------------------------------------------------------------------
// One 128x128x128 chunk GEMM; 16 warps, warp tile 32x32.
// A tile: 272B rows (ldsm4). W tile: 256B rows, gmem-preswizzled (ldsm4t).
// ---------------------------------------------------------------------------
__device__ __forceinline__ void gemm_chunk(uint32_t Abase, uint32_t Wbase,
                                           int lane, int m0, int n0,
                                           float (&acc)[2][4][4]) {
    const uint32_t a_off = Abase + (uint32_t)(m0 + (lane & 15)) * ROWB + (lane >> 4) * 16;
    const int rb = ((lane >> 3) & 1) * 8 + (lane & 7);
    const int s0 = (n0 >> 3) + (lane >> 4);
    const uint32_t b_base0 = Wbase + (uint32_t)rb * 256 +
                             ((uint32_t)((s0 + 0) ^ (rb & 7)) << 4);
    const uint32_t b_base1 = Wbase + (uint32_t)rb * 256 +
                             ((uint32_t)((s0 + 2) ^ (rb & 7)) << 4);

    #pragma unroll
    for (int ks = 0; ks < 8; ks++) {
        const uint32_t k0 = ks * 16;
        uint32_t a[2][4];
        #pragma unroll
        for (int mt = 0; mt < 2; mt++)
            ldsm4(a[mt][0], a[mt][1], a[mt][2], a[mt][3],
                  a_off + mt * 16 * ROWB + k0 * 2);
        uint32_t b[4][2];
        {
            uint32_t r0, r1, r2, r3;
            ldsm4t(r0, r1, r2, r3, b_base0 + ks * 4096);
            b[0][0] = r0; b[0][1] = r1; b[1][0] = r2; b[1][1] = r3;
            ldsm4t(r0, r1, r2, r3, b_base1 + ks * 4096);
            b[2][0] = r0; b[2][1] = r1; b[3][0] = r2; b[3][1] = r3;
        }
        #pragma unroll
        for (int mt = 0; mt < 2; mt++)
            #pragma unroll
            for (int nb = 0; nb < 4; nb++)
                mma_f16(acc[mt][nb], a[mt][0], a[mt][1], a[mt][2], a[mt][3],
                        b[nb][0], b[nb][1]);
    }
}

// ---------------------------------------------------------------------------
// Kernel 3: fused main kernel. grid = (3, 384), 512 threads, 1 CTA/SM.
// Bulk-staged weights + prologue operands; 3 syncs per jc-chunk.
// ---------------------------------------------------------------------------
__global__ __launch_bounds__(NTHREADS, 1)
void k_main(const float* __restrict__ edge_vec,
            const float* __restrict__ b_out,
            const float* __restrict__ tr_scale,
            const float* __restrict__ tr_bias,
            const float* __restrict__ b_t1,
            const float* __restrict__ b_t2,
            float* __restrict__ out) {
    extern __shared__ char smem[];
    const uint32_t sb = smem_u32(smem);
    const int tid = threadIdx.x;
    const int wid = tid >> 5;
    const int lane = tid & 31;
    const int a = blockIdx.y;
    const int bb = blockIdx.x * BM;

    const uint32_t mb0 = sb + MBAR_OFF;
    const uint32_t mb1 = sb + MBAR_OFF + 8;
    const uint32_t mb2 = sb + MBAR_OFF + 16;
    const uint32_t Wb0 = sb + WB0_OFF;
    const uint32_t Wb1 = sb + WB1_OFF;
    const uint32_t Ah  = sb + A_H_OFF;

    if (tid == 0) {
        MBARRIER_INIT(mb0, 1);
        MBARRIER_INIT(mb1, 1);
        MBARRIER_INIT(mb2, 1);
        issue_bulk(Wb0, g_w1c, mb0);                         // W1 chunk 0
        issue_bulk(Wb1, g_w2c, mb1);                         // W2 chunk 0
        expect_tx(mb2, 32768);                               // m_a + right slice
        bulk_cp(Ah,         g_M + (size_t)a * 4096, 16384, mb2);
        bulk_cp(Ah + 16384, g_rightB + (size_t)blockIdx.x * 4096, 16384, mb2);
    }

    float* s_bias32 = (float*)(smem + BIAS_OFF);
    float* s_scale = s_bias32;
    float* s_bias  = s_bias32 + 128;
    float* s_b1    = s_bias32 + 256;
    float* s_b2    = s_bias32 + 768;
    float* s_bout  = s_bias32 + 896;
    for (int i = tid; i < F_DIM; i += NTHREADS) {
        s_scale[i] = tr_scale[i];
        s_bias[i]  = tr_bias[i];
        s_b2[i]    = b_t2[i];
        s_bout[i]  = b_out[i];
    }
    for (int i = tid; i < H_DIM; i += NTHREADS) s_b1[i] = b_t1[i];
    __syncthreads();                  // mbarrier inits visible to all
    MBARRIER_WAIT_PARITY(mb2, 0);     // m_a + right resident

    float* Sf = (float*)(smem + A_H_OFF);       // m_a[d][f] at [0,4096), rightT[c][r] at [4096,8192)

    // ---- e = right @ M_a + edge + b_out (fp32, f32x2) -> gmem; LN -> A_LN fp16
    {
        const int ty = tid >> 4, tx = tid & 15;
        const int r0 = ty * 4, c0 = tx * 8;
        unsigned long long acc2[4][4];
        #pragma unroll
        for (int i = 0; i < 4; i++)
            #pragma unroll
            for (int q = 0; q < 4; q++) acc2[i][q] = 0ull;

        #pragma unroll 4
        for (int k = 0; k < C_DIM; k++) {
            ulonglong2 bA = *reinterpret_cast<const ulonglong2*>(Sf + k * 128 + c0);
            ulonglong2 bB = *reinterpret_cast<const ulonglong2*>(Sf + k * 128 + c0 + 4);
            unsigned long long bv2[4] = { bA.x, bA.y, bB.x, bB.y };
            #pragma unroll
            for (int i = 0; i < 4; i++) {
                float av = Sf[4096 + k * 128 + r0 + i];   // rightT[c][r]
                unsigned long long av2 = pack2(av, av);
                #pragma unroll
                for (int q = 0; q < 4; q++) fma2(acc2[i][q], av2, bv2[q]);
            }
        }
        float acc[4][8];
        #pragma unroll
        for (int i = 0; i < 4; i++)
            #pragma unroll
            for (int q = 0; q < 4; q++)
                unpack2(acc[i][q * 2], acc[i][q * 2 + 1], acc2[i][q]);

        const float* ep = edge_vec + ((long)(a * A_DIM) + bb) * F_DIM;
        float* op = out + ((long)(a * A_DIM) + bb) * F_DIM;
        float rs[4], rq[4];
        #pragma unroll
        for (int i = 0; i < 4; i++) {
            const int r = r0 + i;
            float4 e0 = *reinterpret_cast<const float4*>(ep + r * F_DIM + c0);
            float4 e1 = *reinterpret_cast<const float4*>(ep + r * F_DIM + c0 + 4);
            acc[i][0] += e0.x + s_bout[c0+0]; acc[i][1] += e0.y + s_bout[c0+1];
            acc[i][2] += e0.z + s_bout[c0+2]; acc[i][3] += e0.w + s_bout[c0+3];
            acc[i][4] += e1.x + s_bout[c0+4]; acc[i][5] += e1.y + s_bout[c0+5];
            acc[i][6] += e1.z + s_bout[c0+6]; acc[i][7] += e1.w + s_bout[c0+7];
            float4 o0 = make_float4(acc[i][0], acc[i][1], acc[i][2], acc[i][3]);
            float4 o1 = make_float4(acc[i][4], acc[i][5], acc[i][6], acc[i][7]);
            *reinterpret_cast<float4*>(op + r * F_DIM + c0) = o0;
            *reinterpret_cast<float4*>(op + r * F_DIM + c0 + 4) = o1;
            float s = 0.0f, q = 0.0f;
            #pragma unroll
            for (int j = 0; j < 8; j++) { s += acc[i][j]; q += acc[i][j] * acc[i][j]; }
            rs[i] = s; rq[i] = q;
        }
        #pragma unroll
        for (int off = 1; off < 16; off <<= 1) {
            #pragma unroll
            for (int i = 0; i < 4; i++) {
                rs[i] += __shfl_xor_sync(~0u, rs[i], off);
                rq[i] += __shfl_xor_sync(~0u, rq[i], off);
            }
        }
        #pragma unroll
        for (int i = 0; i < 4; i++) {
            const float mu = rs[i] * (1.0f / F_DIM);
            const float var = rq[i] * (1.0f / F_DIM) - mu * mu;
            const float rstd = rsqrtf(var + EPS);
            __half2 h[4];
            #pragma unroll
            for (int jq = 0; jq < 4; jq++) {
                float l0 = (acc[i][jq*2+0] - mu) * rstd * s_scale[c0+jq*2+0] + s_bias[c0+jq*2+0];
                float l1 = (acc[i][jq*2+1] - mu) * rstd * s_scale[c0+jq*2+1] + s_bias[c0+jq*2+1];
                h[jq] = __floats2half2_rn(l0, l1);
            }
            *reinterpret_cast<uint4*>(smem + A_LN_OFF + (r0 + i) * ROWB + c0 * 2) =
                *reinterpret_cast<uint4*>(h);
        }
    }
    __syncthreads();   // LN tile visible; Sf reads done (A_H free for h)

    // ---- transition MLP: 4 j-chunks, 3 syncs each ----
    const int m0 = (wid >> 2) * 32;
    const int n0 = (wid & 3) * 32;
    const int g = lane >> 2, tig = lane & 3;
    const uint32_t Aln = sb + A_LN_OFF;

    float oacc[2][4][4];
    #pragma unroll
    for (int mt = 0; mt < 2; mt++)
        #pragma unroll
        for (int nb = 0; nb < 4; nb++)
            #pragma unroll
            for (int q = 0; q < 4; q++) oacc[mt][nb][q] = 0.0f;

    int p0 = 0, p1 = 0;
    #pragma unroll 1
    for (int jc = 0; jc < 4; jc++) {
        float hacc[2][4][4];
        #pragma unroll
        for (int mt = 0; mt < 2; mt++)
            #pragma unroll
            for (int nb = 0; nb < 4; nb++)
                #pragma unroll
                for (int q = 0; q < 4; q++) hacc[mt][nb][q] = 0.0f;

        MBARRIER_WAIT_PARITY(mb0, p0); p0 ^= 1;       // W1_jc resident
        __syncthreads();                               // sync1
        gemm_chunk(Aln, Wb0, lane, m0, n0, hacc);

        // relu -> A_H (prev readers of A_H finished before sync1)
        #pragma unroll
        for (int mt = 0; mt < 2; mt++) {
            const int r = m0 + mt * 16 + g;
            #pragma unroll
            for (int nb = 0; nb < 4; nb++) {
                const int c = n0 + nb * 8 + 2 * tig;
                const float b0 = s_b1[jc * 128 + c];
                const float b1 = s_b1[jc * 128 + c + 1];
                __half2 v0 = __floats2half2_rn(fmaxf(hacc[mt][nb][0] + b0, 0.0f),
                                               fmaxf(hacc[mt][nb][1] + b1, 0.0f));
                __half2 v1 = __floats2half2_rn(fmaxf(hacc[mt][nb][2] + b0, 0.0f),
                                               fmaxf(hacc[mt][nb][3] + b1, 0.0f));
                *reinterpret_cast<__half2*>(smem + A_H_OFF + r * ROWB + c * 2) = v0;
                *reinterpret_cast<__half2*>(smem + A_H_OFF + (r + 8) * ROWB + c * 2) = v1;
            }
        }

        MBARRIER_WAIT_PARITY(mb1, p1); p1 ^= 1;       // W2_jc resident
        __syncthreads();                               // sync2: h visible + WB0 free
        if (jc < 3 && tid == 0)
            issue_bulk(Wb0, g_w1c + (jc + 1) * 16384, mb0);

        gemm_chunk(Ah, Wb1, lane, m0, n0, oacc);
        __syncthreads();                               // sync3: WB1 free
        if (jc < 3 && tid == 0)
            issue_bulk(Wb1, g_w2c + (jc + 1) * 16384, mb1);
    }

    // ---- epilogue: out = e + O + b_t2 ----
    {
        float* op = out + ((long)(a * A_DIM) + bb) * F_DIM;
        #pragma unroll
        for (int mt = 0; mt < 2; mt++) {
            const int r = m0 + mt * 16 + g;
            #pragma unroll
            for (int nb = 0; nb < 4; nb++) {
                const int c = n0 + nb * 8 + 2 * tig;
                const float b20 = s_b2[c], b21 = s_b2[c + 1];
                float2 e0 = *reinterpret_cast<const float2*>(op + r * F_DIM + c);
                float2 e1 = *reinterpret_cast<const float2*>(op + (r + 8) * F_DIM + c);
                float2 o0, o1;
                o0.x = e0.x + oacc[mt][nb][0] + b20;
                o0.y = e0.y + oacc[mt][nb][1] + b21;
                o1.x = e1.x + oacc[mt][nb][2] + b20;
                o1.y = e1.y + oacc[mt][nb][3] + b21;
                *reinterpret_cast<float2*>(op + r * F_DIM + c) = o0;
                *reinterpret_cast<float2*>(op + (r + 8) * F_DIM + c) = o1;
            }
        }
    }
}

// ---------------------------------------------------------------------------
// Launch
// ---------------------------------------------------------------------------
extern "C" void kernel_launch(void* const* d_in, const int* in_sizes, int n_in,
                              void* d_out, int out_size) {
    const float* node_vec    = (const float*)d_in[0];
    const float* edge_vec    = (const float*)d_in[1];
    const float* node_mask   = (const float*)d_in[2];
    const float* op_ln_scale = (const float*)d_in[4];
    const float* op_ln_bias  = (const float*)d_in[5];
    const float* w_left      = (const float*)d_in[6];
    const float* b_left      = (const float*)d_in[7];
    const float* w_right     = (const float*)d_in[8];
    const float* b_right     = (const float*)d_in[9];
    const float* w_out       = (const float*)d_in[10];
    const float* b_out       = (const float*)d_in[11];
    const float* tr_ln_scale = (const float*)d_in[12];
    const float* tr_ln_bias  = (const float*)d_in[13];
    const float* w_t1        = (const float*)d_in[14];
    const float* b_t1        = (const float*)d_in[15];
    const float* w_t2        = (const float*)d_in[16];
    const float* b_t2        = (const float*)d_in[17];
    float* out = (float*)d_out;

    static bool attr_set = false;
    if (!attr_set) {
        cudaFuncSetAttribute(k_main, cudaFuncAttributeMaxDynamicSharedMemorySize,
                             (int)SMEM_BYTES);
        attr_set = true;
    }

    k_pre<<<A_DIM, F_DIM>>>(node_vec, node_mask, op_ln_scale, op_ln_bias,
                            w_left, b_left, w_right, b_right, w_t1, w_t2);
    k_M<<<A_DIM / 8, 512>>>(w_out);
    k_main<<<dim3(A_DIM / BM, A_DIM), NTHREADS, SMEM_BYTES>>>(
        edge_vec, b_out, tr_ln_scale, tr_ln_bias, b_t1, b_t2, out);
}